// round 16
// baseline (speedup 1.0000x reference)
#include <cuda_runtime.h>
#include <cuda_fp16.h>
#include <cstdint>

// Problem constants
#define NVEC   32768
#define DIM    256
#define NCODE  4096

// Output layout (all fp32): [quantize 8388608][diff 1][ind 32768]
#define Q_ELEMS   (NVEC * DIM)
#define DIFF_OFF  Q_ELEMS
#define IND_OFF   (Q_ELEMS + 1)

#define NCAND  8
#define MTILE  64
#define MARGIN 0.25f

// Scratch
__device__ float  g_embedT[NCODE * DIM];            // [code][dim] fp32
__device__ __align__(16) __half g_Bh[NCODE * DIM];  // [code][dim] fp16 codes
__device__ float  g_enorm[NCODE];
__device__ int    g_cand[NVEC * NCAND];
__device__ float  g_gap[NVEC];                      // approx top2-top1 gap
__device__ double g_part[8192];

// ---------------------------------------------------------------------------
__device__ __forceinline__ uint32_t smem_u32(const void* p) {
    uint32_t a;
    asm("{ .reg .u64 t; cvta.to.shared.u64 t, %1; cvt.u32.u64 %0, t; }"
        : "=r"(a) : "l"(p));
    return a;
}
__device__ __forceinline__ void ldsm_x4(uint32_t r[4], uint32_t addr) {
    asm volatile("ldmatrix.sync.aligned.m8n8.x4.shared.b16 {%0,%1,%2,%3}, [%4];"
                 : "=r"(r[0]), "=r"(r[1]), "=r"(r[2]), "=r"(r[3]) : "r"(addr));
}
__device__ __forceinline__ void mma_f16(float c[4], const uint32_t a[4],
                                        const uint32_t b0, const uint32_t b1) {
    asm volatile(
        "mma.sync.aligned.m16n8k16.row.col.f32.f16.f16.f32 "
        "{%0,%1,%2,%3}, {%4,%5,%6,%7}, {%8,%9}, {%0,%1,%2,%3};"
        : "+f"(c[0]), "+f"(c[1]), "+f"(c[2]), "+f"(c[3])
        : "r"(a[0]), "r"(a[1]), "r"(a[2]), "r"(a[3]), "r"(b0), "r"(b1));
}
#define CP_ASYNC16(dst, src) \
    asm volatile("cp.async.cg.shared.global [%0], [%1], 16;" \
                 :: "r"(dst), "l"(src) : "memory")
#define CP_COMMIT()  asm volatile("cp.async.commit_group;" ::: "memory")
#define CP_WAIT2()   asm volatile("cp.async.wait_group 2;" ::: "memory")

// ---------------------------------------------------------------------------
// SMEM: A resident (64 x 264 halves, 528B rows, fp16), block-shared.
// B: per-warp private pipeline — 8 warps x 4 stages x (16 codes x 64 k,
// 144B rows). No __syncthreads in the main loop.
#define A_ROW_B   528
#define B_BASE    33792            // 64*528
#define B_ROW_B   144
#define B_WBUF    2304             // 16*144 per warp-stage
#define SMEM_TOT  (B_BASE + 8 * 4 * B_WBUF)   // 107520 -> 2 CTAs/SM

// ===========================================================================
// Warp-autonomous fp16 mma GEMM + per-thread top-2 (8 slots) + merged top-8.
// Grid 512 (64 rows/CTA), block 256 (round-13/15 structure, validated).
// ===========================================================================
__global__ __launch_bounds__(256, 2)
void vq_mma_kernel(const float* __restrict__ x) {
    extern __shared__ char smem[];
    const uint32_t sb = smem_u32(smem);
    const int t    = threadIdx.x;
    const int wid  = t >> 5, lane = t & 31;
    const int n0   = blockIdx.x * MTILE;

    // ---- convert A (64 x rows) to fp16 in smem (block-wide, once) ----------
    {
        const float4* xg4 = (const float4*)(x + (size_t)n0 * DIM);
#pragma unroll
        for (int i = 0; i < 16; i++) {
            const int f   = t + i * 256;          // 0..4095 float4
            const int row = f >> 6;
            const int c4  = f & 63;
            float4 v = xg4[f];
            __half hx = __float2half_rn(v.x), hy = __float2half_rn(v.y);
            __half hz = __float2half_rn(v.z), hw = __float2half_rn(v.w);
            const int off = row * A_ROW_B + c4 * 8;
            *(__half2*)(smem + off)     = __halves2half2(hx, hy);
            *(__half2*)(smem + off + 4) = __halves2half2(hz, hw);
        }
    }
    __syncthreads();   // A visible to all warps

    const uint32_t aBase0 = sb + (uint32_t)(lane & 15) * A_ROW_B
                          + (uint32_t)(((lane >> 4) & 1) * 16);
    const uint32_t bWBase = sb + B_BASE + (uint32_t)(wid * 4) * B_WBUF
                          + (uint32_t)((lane & 7) + ((lane >> 4) & 1) * 8) * B_ROW_B
                          + (uint32_t)(((lane >> 3) & 1) * 16);

    // per-warp B chunk (16 codes x 64 k fp16 = 2KB): 128 x 16B, 4 per lane
    auto issueB = [&](int ch) {
        const int nb = (ch >> 2) * 128 + wid * 16;
        const int kb = (ch & 3) * 64;
        const uint32_t bufb = sb + B_BASE + (uint32_t)(wid * 4 + (ch & 3)) * B_WBUF;
#pragma unroll
        for (int j = 0; j < 4; j++) {
            const int s = lane + j * 32;         // 0..127
            const int r = s >> 3;                // 0..15
            const int q = s & 7;                 // 0..7
            const uint32_t dst = bufb + (uint32_t)r * B_ROW_B + (uint32_t)q * 16;
            const __half* srcp = g_Bh + (size_t)(nb + r) * DIM + kb + q * 8;
            CP_ASYNC16(dst, srcp);
        }
    };

    float acc[4][2][4];
#pragma unroll
    for (int mt = 0; mt < 4; mt++)
#pragma unroll
        for (int nt = 0; nt < 2; nt++)
#pragma unroll
            for (int q = 0; q < 4; q++) acc[mt][nt][q] = 0.f;

    float t2v[8][2];
    int   t2i[8][2];
#pragma unroll
    for (int q = 0; q < 8; q++) {
        t2v[q][0] = 3.4e38f; t2v[q][1] = 3.4e38f;
        t2i[q][0] = 0; t2i[q][1] = 1;
    }

    issueB(0); CP_COMMIT();
    issueB(1); CP_COMMIT();
    issueB(2); CP_COMMIT();

    const float2* en2 = (const float2*)g_enorm;

    for (int i = 0; i < 128; i++) {
        CP_WAIT2();
        __syncwarp();

        if (i + 3 < 128) issueB(i + 3);
        CP_COMMIT();

        const uint32_t bufo = (uint32_t)(i & 3) * B_WBUF;
        const uint32_t kcb  = (uint32_t)(i & 3) * 64;

#pragma unroll
        for (int kk = 0; kk < 4; kk++) {
            const uint32_t kab = (kcb + kk * 16) * 2;
            uint32_t bh[4];
            ldsm_x4(bh, bWBase + bufo + (uint32_t)kk * 32);
            uint32_t ah[4];
#pragma unroll
            for (int mt = 0; mt < 4; mt++) {
                ldsm_x4(ah, aBase0 + (uint32_t)mt * (16 * A_ROW_B) + kab);
                mma_f16(acc[mt][0], ah, bh[0], bh[1]);
                mma_f16(acc[mt][1], ah, bh[2], bh[3]);
            }
        }

        if ((i & 3) == 3) {
            const int cbase = (i >> 2) * 128 + wid * 16;
#pragma unroll
            for (int mt = 0; mt < 4; mt++)
#pragma unroll
                for (int nt = 0; nt < 2; nt++) {
                    const int j0 = cbase + nt * 8 + (lane & 3) * 2;
                    const float2 en = __ldg(&en2[j0 >> 1]);
                    float d[4];
                    d[0] = fmaf(-2.f, acc[mt][nt][0], en.x);
                    d[1] = fmaf(-2.f, acc[mt][nt][1], en.y);
                    d[2] = fmaf(-2.f, acc[mt][nt][2], en.x);
                    d[3] = fmaf(-2.f, acc[mt][nt][3], en.y);
                    const int jj[4] = {j0, j0 + 1, j0, j0 + 1};
#pragma unroll
                    for (int u = 0; u < 4; u++) {
                        const int q = mt * 2 + (u >> 1);
                        const float v = d[u];
                        if (v < t2v[q][1]) {
                            if (v < t2v[q][0]) {
                                t2v[q][1] = t2v[q][0]; t2i[q][1] = t2i[q][0];
                                t2v[q][0] = v;         t2i[q][0] = jj[u];
                            } else {
                                t2v[q][1] = v; t2i[q][1] = jj[u];
                            }
                        }
                    }
                    acc[mt][nt][0] = 0.f; acc[mt][nt][1] = 0.f;
                    acc[mt][nt][2] = 0.f; acc[mt][nt][3] = 0.f;
                }
        }
    }

    // ---- merge: 32 sources x top-2 per row -> top-8 + gap ------------------
    __syncthreads();
    float* sV = (float*)smem;                 // [64 rows][32 src][2]
    int*   sI = (int*)(smem + 64 * 32 * 2 * 4);
    const int src = wid * 4 + (lane & 3);
#pragma unroll
    for (int mt = 0; mt < 4; mt++)
#pragma unroll
        for (int h = 0; h < 2; h++) {
            const int q = mt * 2 + h;
            const int row = mt * 16 + h * 8 + (lane >> 2);
            const int base = (row * 32 + src) * 2;
            sV[base + 0] = t2v[q][0]; sI[base + 0] = t2i[q][0];
            sV[base + 1] = t2v[q][1]; sI[base + 1] = t2i[q][1];
        }
    __syncthreads();
    if (t < MTILE) {
        float v8[NCAND];
        int   i8[NCAND];
#pragma unroll
        for (int c = 0; c < NCAND; c++) { v8[c] = 3.4e38f; i8[c] = c; }
        const int base = t * 64;
        for (int e = 0; e < 64; e++) {
            float v = sV[base + e];
            int   id = sI[base + e];
            if (v < v8[NCAND - 1]) {
                int p = NCAND - 1;
                while (p > 0 && v < v8[p - 1]) {
                    v8[p] = v8[p - 1]; i8[p] = i8[p - 1]; p--;
                }
                v8[p] = v; i8[p] = id;
            }
        }
        const int n = n0 + t;
#pragma unroll
        for (int c = 0; c < NCAND; c++) g_cand[n * NCAND + c] = i8[c];
        g_gap[n] = v8[1] - v8[0];
    }
}

// ===========================================================================
// Prep kernels
// ===========================================================================
__global__ void enorm_kernel(const float* __restrict__ embed) {
    int j = blockIdx.x * blockDim.x + threadIdx.x;
    float s = 0.f;
#pragma unroll 8
    for (int d = 0; d < DIM; d++) {
        float v = embed[d * NCODE + j];
        s += v * v;
    }
    g_enorm[j] = s;
}

__global__ void transpose_split_kernel(const float* __restrict__ embed) {
    __shared__ float tile[32][33];
    int j0 = blockIdx.x * 32;
    int d0 = blockIdx.y * 32;
    int tx = threadIdx.x, ty = threadIdx.y;  // 32 x 8
#pragma unroll
    for (int i = 0; i < 4; i++)
        tile[ty + i * 8][tx] = embed[(size_t)(d0 + ty + i * 8) * NCODE + j0 + tx];
    __syncthreads();
#pragma unroll
    for (int i = 0; i < 4; i++) {
        float v = tile[tx][ty + i * 8];
        size_t o = (size_t)(j0 + ty + i * 8) * DIM + d0 + tx;
        g_embedT[o] = v;
        g_Bh[o] = __float2half_rn(v);
    }
}

// ===========================================================================
// Margin-gated rescore + gather + diff. One warp per row. SMEM-FREE.
// Fast path (gap > MARGIN): winner = cand[0].
// Slow path: exact sequential k-order fp32 dot (validated rounding order),
// reading x (lane-broadcast) and candidate rows directly from global.
// ===========================================================================
__global__ __launch_bounds__(128)
void rescore_gather_kernel(const float* __restrict__ input,
                           float* __restrict__ out) {
    __shared__ double ws[4];

    const int wid = threadIdx.x >> 5, lane = threadIdx.x & 31;
    const int n = blockIdx.x * 4 + wid;

    const float4* x4 = (const float4*)(input + (size_t)n * DIM);
    float4 v0 = x4[lane], v1 = x4[lane + 32];

    const float gap = __ldg(&g_gap[n]);
    int widx;

    if (gap > MARGIN) {
        // ---- fast path: approx winner is provably the argmin --------------
        widx = __ldg(&g_cand[n * NCAND]);
    } else {
        // ---- slow path: exact rescore, global reads -----------------------
        float dist = 3.4e38f;
        int   cidx = 0x7fffffff;
        if (lane < NCAND) {
            const int cand = __ldg(&g_cand[n * NCAND + lane]);
            const float4* ev = (const float4*)(g_embedT + (size_t)cand * DIM);
            float dot = 0.f;
#pragma unroll 8
            for (int k4 = 0; k4 < 64; k4++) {
                float4 xx = __ldg(&x4[k4]);    // same addr all lanes: broadcast
                float4 ee = __ldg(&ev[k4]);
                dot += xx.x * ee.x;
                dot += xx.y * ee.y;
                dot += xx.z * ee.z;
                dot += xx.w * ee.w;
            }
            dist = __ldg(&g_enorm[cand]) - 2.0f * dot;
            cidx = cand;
        }
        float bv = dist; int bi = cidx;
#pragma unroll
        for (int l = 0; l < NCAND; l++) {
            float ov = __shfl_sync(0xffffffffu, dist, l);
            int   oi = __shfl_sync(0xffffffffu, cidx, l);
            if (ov < bv || (ov == bv && oi < bi)) { bv = ov; bi = oi; }
        }
        widx = __shfl_sync(0xffffffffu, bi, 0);
    }

    // gather winner row (coalesced; L2-hot on slow path)
    const float4* eg = (const float4*)(g_embedT + (size_t)widx * DIM);
    float4 oa = __ldg(&eg[lane]);
    float4 ob = __ldg(&eg[lane + 32]);

    float4* o4 = (float4*)(out + (size_t)n * DIM);
    o4[lane]      = oa;
    o4[lane + 32] = ob;
    if (lane == 0)
        out[IND_OFF + n] = (float)widx;

    float dx0 = oa.x - v0.x, dx1 = oa.y - v0.y, dx2 = oa.z - v0.z, dx3 = oa.w - v0.w;
    float dy0 = ob.x - v1.x, dy1 = ob.y - v1.y, dy2 = ob.z - v1.z, dy3 = ob.w - v1.w;
    float s = dx0 * dx0 + dx1 * dx1 + dx2 * dx2 + dx3 * dx3
            + dy0 * dy0 + dy1 * dy1 + dy2 * dy2 + dy3 * dy3;
    double sd = (double)s;
#pragma unroll
    for (int off = 16; off; off >>= 1)
        sd += __shfl_xor_sync(0xffffffffu, sd, off);
    if (lane == 0) ws[wid] = sd;
    __syncthreads();
    if (threadIdx.x == 0) {
        double tot = 0.0;
#pragma unroll
        for (int i = 0; i < 4; i++) tot += ws[i];
        g_part[blockIdx.x] = tot;
    }
}

__global__ void diff_kernel(float* __restrict__ out) {
    __shared__ double s[128];
    int t = threadIdx.x;
    double a = 0.0;
    for (int i = 0; i < 64; i++) a += g_part[t + i * 128];
    s[t] = a;
    __syncthreads();
    if (t == 0) {
        double tot = 0.0;
        for (int i = 0; i < 128; i++) tot += s[i];
        out[DIFF_OFF] = (float)(tot / (double)Q_ELEMS);
    }
}

// ===========================================================================
extern "C" void kernel_launch(void* const* d_in, const int* in_sizes, int n_in,
                              void* d_out, int out_size) {
    const float* input = (const float*)d_in[0];   // [8,64,64,256]
    const float* embed = (const float*)d_in[1];   // [256,4096]
    float* out = (float*)d_out;

    enorm_kernel<<<NCODE / 256, 256>>>(embed);
    transpose_split_kernel<<<dim3(NCODE / 32, DIM / 32), dim3(32, 8)>>>(embed);

    cudaFuncSetAttribute(vq_mma_kernel,
                         cudaFuncAttributeMaxDynamicSharedMemorySize, SMEM_TOT);
    vq_mma_kernel<<<NVEC / MTILE, 256, SMEM_TOT>>>(input);

    rescore_gather_kernel<<<NVEC / 4, 128>>>(input, out);
    diff_kernel<<<1, 128>>>(out);
}

// round 17
// speedup vs baseline: 1.0141x; 1.0141x over previous
#include <cuda_runtime.h>
#include <cuda_fp16.h>
#include <cstdint>

// Problem constants
#define NVEC   32768
#define DIM    256
#define NCODE  4096

// Output layout (all fp32): [quantize 8388608][diff 1][ind 32768]
#define Q_ELEMS   (NVEC * DIM)
#define DIFF_OFF  Q_ELEMS
#define IND_OFF   (Q_ELEMS + 1)

#define NCAND  8
#define MTILE  64
#define MARGIN 0.25f
#define NBLK_G (NVEC / MTILE)      // 512 GEMM blocks
#define NBLK_R (NVEC / 4)          // 8192 rescore blocks
#define NPART  (NBLK_G + NBLK_R)   // 8704 diff partials

// Scratch
__device__ float  g_embedT[NCODE * DIM];            // [code][dim] fp32
__device__ __align__(16) __half g_Bh[NCODE * DIM];  // [code][dim] fp16 codes
__device__ float  g_enorm[NCODE];
__device__ int    g_cand[NVEC * NCAND];
__device__ float  g_gap[NVEC];                      // approx top2-top1 gap
__device__ double g_part[NPART];

// ---------------------------------------------------------------------------
__device__ __forceinline__ uint32_t smem_u32(const void* p) {
    uint32_t a;
    asm("{ .reg .u64 t; cvta.to.shared.u64 t, %1; cvt.u32.u64 %0, t; }"
        : "=r"(a) : "l"(p));
    return a;
}
__device__ __forceinline__ void ldsm_x4(uint32_t r[4], uint32_t addr) {
    asm volatile("ldmatrix.sync.aligned.m8n8.x4.shared.b16 {%0,%1,%2,%3}, [%4];"
                 : "=r"(r[0]), "=r"(r[1]), "=r"(r[2]), "=r"(r[3]) : "r"(addr));
}
__device__ __forceinline__ void mma_f16(float c[4], const uint32_t a[4],
                                        const uint32_t b0, const uint32_t b1) {
    asm volatile(
        "mma.sync.aligned.m16n8k16.row.col.f32.f16.f16.f32 "
        "{%0,%1,%2,%3}, {%4,%5,%6,%7}, {%8,%9}, {%0,%1,%2,%3};"
        : "+f"(c[0]), "+f"(c[1]), "+f"(c[2]), "+f"(c[3])
        : "r"(a[0]), "r"(a[1]), "r"(a[2]), "r"(a[3]), "r"(b0), "r"(b1));
}
#define CP_ASYNC16(dst, src) \
    asm volatile("cp.async.cg.shared.global [%0], [%1], 16;" \
                 :: "r"(dst), "l"(src) : "memory")
#define CP_COMMIT()  asm volatile("cp.async.commit_group;" ::: "memory")
#define CP_WAIT2()   asm volatile("cp.async.wait_group 2;" ::: "memory")

// ---------------------------------------------------------------------------
// SMEM: A resident (64 x 264 halves, 528B rows, fp16), block-shared.
// B: per-warp private pipeline — 8 warps x 4 stages x (16 codes x 64 k,
// 144B rows). No __syncthreads in the main loop.
#define A_ROW_B   528
#define B_BASE    33792            // 64*528
#define B_ROW_B   144
#define B_WBUF    2304             // 16*144 per warp-stage
#define SMEM_TOT  (B_BASE + 8 * 4 * B_WBUF)   // 107520 -> 2 CTAs/SM

// ===========================================================================
// Warp-autonomous fp16 mma GEMM + top-8 merge + FUSED fast-path output.
// Grid 512 (64 rows/CTA), block 256 (round-13/15 mainloop, validated).
// ===========================================================================
__global__ __launch_bounds__(256, 2)
void vq_mma_kernel(const float* __restrict__ x, float* __restrict__ out) {
    extern __shared__ char smem[];
    const uint32_t sb = smem_u32(smem);
    const int t    = threadIdx.x;
    const int wid  = t >> 5, lane = t & 31;
    const int n0   = blockIdx.x * MTILE;
    const float4* xg4 = (const float4*)(x + (size_t)n0 * DIM);

    // ---- convert A (64 x rows) to fp16 in smem (block-wide, once) ----------
#pragma unroll
    for (int i = 0; i < 16; i++) {
        const int f   = t + i * 256;          // 0..4095 float4
        const int row = f >> 6;
        const int c4  = f & 63;
        float4 v = xg4[f];
        __half hx = __float2half_rn(v.x), hy = __float2half_rn(v.y);
        __half hz = __float2half_rn(v.z), hw = __float2half_rn(v.w);
        const int off = row * A_ROW_B + c4 * 8;
        *(__half2*)(smem + off)     = __halves2half2(hx, hy);
        *(__half2*)(smem + off + 4) = __halves2half2(hz, hw);
    }
    __syncthreads();   // A visible to all warps

    const uint32_t aBase0 = sb + (uint32_t)(lane & 15) * A_ROW_B
                          + (uint32_t)(((lane >> 4) & 1) * 16);
    const uint32_t bWBase = sb + B_BASE + (uint32_t)(wid * 4) * B_WBUF
                          + (uint32_t)((lane & 7) + ((lane >> 4) & 1) * 8) * B_ROW_B
                          + (uint32_t)(((lane >> 3) & 1) * 16);

    // per-warp B chunk (16 codes x 64 k fp16 = 2KB): 128 x 16B, 4 per lane
    auto issueB = [&](int ch) {
        const int nb = (ch >> 2) * 128 + wid * 16;
        const int kb = (ch & 3) * 64;
        const uint32_t bufb = sb + B_BASE + (uint32_t)(wid * 4 + (ch & 3)) * B_WBUF;
#pragma unroll
        for (int j = 0; j < 4; j++) {
            const int s = lane + j * 32;         // 0..127
            const int r = s >> 3;                // 0..15
            const int q = s & 7;                 // 0..7
            const uint32_t dst = bufb + (uint32_t)r * B_ROW_B + (uint32_t)q * 16;
            const __half* srcp = g_Bh + (size_t)(nb + r) * DIM + kb + q * 8;
            CP_ASYNC16(dst, srcp);
        }
    };

    float acc[4][2][4];
#pragma unroll
    for (int mt = 0; mt < 4; mt++)
#pragma unroll
        for (int nt = 0; nt < 2; nt++)
#pragma unroll
            for (int q = 0; q < 4; q++) acc[mt][nt][q] = 0.f;

    float t2v[8][2];
    int   t2i[8][2];
#pragma unroll
    for (int q = 0; q < 8; q++) {
        t2v[q][0] = 3.4e38f; t2v[q][1] = 3.4e38f;
        t2i[q][0] = 0; t2i[q][1] = 1;
    }

    issueB(0); CP_COMMIT();
    issueB(1); CP_COMMIT();
    issueB(2); CP_COMMIT();

    const float2* en2 = (const float2*)g_enorm;

    for (int i = 0; i < 128; i++) {
        CP_WAIT2();
        __syncwarp();

        if (i + 3 < 128) issueB(i + 3);
        CP_COMMIT();

        const uint32_t bufo = (uint32_t)(i & 3) * B_WBUF;
        const uint32_t kcb  = (uint32_t)(i & 3) * 64;

#pragma unroll
        for (int kk = 0; kk < 4; kk++) {
            const uint32_t kab = (kcb + kk * 16) * 2;
            uint32_t bh[4];
            ldsm_x4(bh, bWBase + bufo + (uint32_t)kk * 32);
            uint32_t ah[4];
#pragma unroll
            for (int mt = 0; mt < 4; mt++) {
                ldsm_x4(ah, aBase0 + (uint32_t)mt * (16 * A_ROW_B) + kab);
                mma_f16(acc[mt][0], ah, bh[0], bh[1]);
                mma_f16(acc[mt][1], ah, bh[2], bh[3]);
            }
        }

        if ((i & 3) == 3) {
            const int cbase = (i >> 2) * 128 + wid * 16;
#pragma unroll
            for (int mt = 0; mt < 4; mt++)
#pragma unroll
                for (int nt = 0; nt < 2; nt++) {
                    const int j0 = cbase + nt * 8 + (lane & 3) * 2;
                    const float2 en = __ldg(&en2[j0 >> 1]);
                    float d[4];
                    d[0] = fmaf(-2.f, acc[mt][nt][0], en.x);
                    d[1] = fmaf(-2.f, acc[mt][nt][1], en.y);
                    d[2] = fmaf(-2.f, acc[mt][nt][2], en.x);
                    d[3] = fmaf(-2.f, acc[mt][nt][3], en.y);
                    const int jj[4] = {j0, j0 + 1, j0, j0 + 1};
#pragma unroll
                    for (int u = 0; u < 4; u++) {
                        const int q = mt * 2 + (u >> 1);
                        const float v = d[u];
                        if (v < t2v[q][1]) {
                            if (v < t2v[q][0]) {
                                t2v[q][1] = t2v[q][0]; t2i[q][1] = t2i[q][0];
                                t2v[q][0] = v;         t2i[q][0] = jj[u];
                            } else {
                                t2v[q][1] = v; t2i[q][1] = jj[u];
                            }
                        }
                    }
                    acc[mt][nt][0] = 0.f; acc[mt][nt][1] = 0.f;
                    acc[mt][nt][2] = 0.f; acc[mt][nt][3] = 0.f;
                }
        }
    }

    // ---- merge: 32 sources x top-2 per row -> top-8 + gap ------------------
    __syncthreads();
    float* sV = (float*)smem;                 // [64 rows][32 src][2]
    int*   sI = (int*)(smem + 64 * 32 * 2 * 4);
    int*   sWin = (int*)(smem + B_BASE);      // [64] fast-path winners (-1 slow)
    const int src = wid * 4 + (lane & 3);
#pragma unroll
    for (int mt = 0; mt < 4; mt++)
#pragma unroll
        for (int h = 0; h < 2; h++) {
            const int q = mt * 2 + h;
            const int row = mt * 16 + h * 8 + (lane >> 2);
            const int base = (row * 32 + src) * 2;
            sV[base + 0] = t2v[q][0]; sI[base + 0] = t2i[q][0];
            sV[base + 1] = t2v[q][1]; sI[base + 1] = t2i[q][1];
        }
    __syncthreads();
    if (t < MTILE) {
        float v8[NCAND];
        int   i8[NCAND];
#pragma unroll
        for (int c = 0; c < NCAND; c++) { v8[c] = 3.4e38f; i8[c] = c; }
        const int base = t * 64;
        for (int e = 0; e < 64; e++) {
            float v = sV[base + e];
            int   id = sI[base + e];
            if (v < v8[NCAND - 1]) {
                int p = NCAND - 1;
                while (p > 0 && v < v8[p - 1]) {
                    v8[p] = v8[p - 1]; i8[p] = i8[p - 1]; p--;
                }
                v8[p] = v; i8[p] = id;
            }
        }
        const int n = n0 + t;
        const float gap = v8[1] - v8[0];
        g_gap[n] = gap;
        if (gap > MARGIN) {
            sWin[t] = i8[0];
        } else {
            sWin[t] = -1;
#pragma unroll
            for (int c = 0; c < NCAND; c++) g_cand[n * NCAND + c] = i8[c];
        }
    }
    __syncthreads();

    // ---- fused fast-path output: warp w handles rows w*8..w*8+7 ------------
    double dsum = 0.0;
#pragma unroll
    for (int r8 = 0; r8 < 8; r8++) {
        const int row = wid * 8 + r8;
        const int widx = sWin[row];
        if (widx >= 0) {
            const float4* eg = (const float4*)(g_embedT + (size_t)widx * DIM);
            float4 oa = __ldg(&eg[lane]);
            float4 ob = __ldg(&eg[lane + 32]);
            const float4* xr = xg4 + row * 64;
            float4 va = xr[lane];
            float4 vb = xr[lane + 32];
            float4* o4 = (float4*)(out + (size_t)(n0 + row) * DIM);
            o4[lane]      = oa;
            o4[lane + 32] = ob;
            if (lane == 0)
                out[IND_OFF + n0 + row] = (float)widx;
            float dx0 = oa.x - va.x, dx1 = oa.y - va.y;
            float dx2 = oa.z - va.z, dx3 = oa.w - va.w;
            float dy0 = ob.x - vb.x, dy1 = ob.y - vb.y;
            float dy2 = ob.z - vb.z, dy3 = ob.w - vb.w;
            dsum += (double)(dx0 * dx0 + dx1 * dx1 + dx2 * dx2 + dx3 * dx3
                           + dy0 * dy0 + dy1 * dy1 + dy2 * dy2 + dy3 * dy3);
        }
    }
#pragma unroll
    for (int off = 16; off; off >>= 1)
        dsum += __shfl_xor_sync(0xffffffffu, dsum, off);
    double* wsum = (double*)(smem + B_BASE + 256);   // [8]
    if (lane == 0) wsum[wid] = dsum;
    __syncthreads();
    if (t == 0) {
        double tot = 0.0;
#pragma unroll
        for (int i = 0; i < 8; i++) tot += wsum[i];
        g_part[blockIdx.x] = tot;
    }
}

// ===========================================================================
// Prep kernels
// ===========================================================================
__global__ void enorm_kernel(const float* __restrict__ embed) {
    int j = blockIdx.x * blockDim.x + threadIdx.x;
    float s = 0.f;
#pragma unroll 8
    for (int d = 0; d < DIM; d++) {
        float v = embed[d * NCODE + j];
        s += v * v;
    }
    g_enorm[j] = s;
}

__global__ void transpose_split_kernel(const float* __restrict__ embed) {
    __shared__ float tile[32][33];
    int j0 = blockIdx.x * 32;
    int d0 = blockIdx.y * 32;
    int tx = threadIdx.x, ty = threadIdx.y;  // 32 x 8
#pragma unroll
    for (int i = 0; i < 4; i++)
        tile[ty + i * 8][tx] = embed[(size_t)(d0 + ty + i * 8) * NCODE + j0 + tx];
    __syncthreads();
#pragma unroll
    for (int i = 0; i < 4; i++) {
        float v = tile[tx][ty + i * 8];
        size_t o = (size_t)(j0 + ty + i * 8) * DIM + d0 + tx;
        g_embedT[o] = v;
        g_Bh[o] = __float2half_rn(v);
    }
}

// ===========================================================================
// Slow-path-only rescore. One warp per row; fast rows exit after one load.
// Slow rows: exact sequential k-order fp32 dot (validated rounding order),
// global reads; then gather + output + diff partial.
// ===========================================================================
__global__ __launch_bounds__(128)
void rescore_gather_kernel(const float* __restrict__ input,
                           float* __restrict__ out) {
    __shared__ double ws[4];

    const int wid = threadIdx.x >> 5, lane = threadIdx.x & 31;
    const int n = blockIdx.x * 4 + wid;

    const float gap = __ldg(&g_gap[n]);
    double dsum = 0.0;

    if (gap <= MARGIN) {
        const float4* x4 = (const float4*)(input + (size_t)n * DIM);
        float4 v0 = x4[lane], v1 = x4[lane + 32];

        float dist = 3.4e38f;
        int   cidx = 0x7fffffff;
        if (lane < NCAND) {
            const int cand = __ldg(&g_cand[n * NCAND + lane]);
            const float4* ev = (const float4*)(g_embedT + (size_t)cand * DIM);
            float dot = 0.f;
#pragma unroll 8
            for (int k4 = 0; k4 < 64; k4++) {
                float4 xx = __ldg(&x4[k4]);    // same addr all lanes: broadcast
                float4 ee = __ldg(&ev[k4]);
                dot += xx.x * ee.x;
                dot += xx.y * ee.y;
                dot += xx.z * ee.z;
                dot += xx.w * ee.w;
            }
            dist = __ldg(&g_enorm[cand]) - 2.0f * dot;
            cidx = cand;
        }
        float bv = dist; int bi = cidx;
#pragma unroll
        for (int l = 0; l < NCAND; l++) {
            float ov = __shfl_sync(0xffffffffu, dist, l);
            int   oi = __shfl_sync(0xffffffffu, cidx, l);
            if (ov < bv || (ov == bv && oi < bi)) { bv = ov; bi = oi; }
        }
        const int widx = __shfl_sync(0xffffffffu, bi, 0);

        const float4* eg = (const float4*)(g_embedT + (size_t)widx * DIM);
        float4 oa = __ldg(&eg[lane]);
        float4 ob = __ldg(&eg[lane + 32]);

        float4* o4 = (float4*)(out + (size_t)n * DIM);
        o4[lane]      = oa;
        o4[lane + 32] = ob;
        if (lane == 0)
            out[IND_OFF + n] = (float)widx;

        float dx0 = oa.x - v0.x, dx1 = oa.y - v0.y;
        float dx2 = oa.z - v0.z, dx3 = oa.w - v0.w;
        float dy0 = ob.x - v1.x, dy1 = ob.y - v1.y;
        float dy2 = ob.z - v1.z, dy3 = ob.w - v1.w;
        float s = dx0 * dx0 + dx1 * dx1 + dx2 * dx2 + dx3 * dx3
                + dy0 * dy0 + dy1 * dy1 + dy2 * dy2 + dy3 * dy3;
        dsum = (double)s;
#pragma unroll
        for (int off = 16; off; off >>= 1)
            dsum += __shfl_xor_sync(0xffffffffu, dsum, off);
    }

    if (lane == 0) ws[wid] = dsum;
    __syncthreads();
    if (threadIdx.x == 0) {
        double tot = 0.0;
#pragma unroll
        for (int i = 0; i < 4; i++) tot += ws[i];
        g_part[NBLK_G + blockIdx.x] = tot;
    }
}

__global__ void diff_kernel(float* __restrict__ out) {
    __shared__ double s[128];
    int t = threadIdx.x;
    double a = 0.0;
    for (int i = 0; i < (NPART + 127) / 128; i++) {
        int idx = t + i * 128;
        if (idx < NPART) a += g_part[idx];
    }
    s[t] = a;
    __syncthreads();
    if (t == 0) {
        double tot = 0.0;
        for (int i = 0; i < 128; i++) tot += s[i];
        out[DIFF_OFF] = (float)(tot / (double)Q_ELEMS);
    }
}

// ===========================================================================
extern "C" void kernel_launch(void* const* d_in, const int* in_sizes, int n_in,
                              void* d_out, int out_size) {
    const float* input = (const float*)d_in[0];   // [8,64,64,256]
    const float* embed = (const float*)d_in[1];   // [256,4096]
    float* out = (float*)d_out;

    enorm_kernel<<<NCODE / 256, 256>>>(embed);
    transpose_split_kernel<<<dim3(NCODE / 32, DIM / 32), dim3(32, 8)>>>(embed);

    cudaFuncSetAttribute(vq_mma_kernel,
                         cudaFuncAttributeMaxDynamicSharedMemorySize, SMEM_TOT);
    vq_mma_kernel<<<NVEC / MTILE, 256, SMEM_TOT>>>(input, out);

    rescore_gather_kernel<<<NVEC / 4, 128>>>(input, out);
    diff_kernel<<<1, 128>>>(out);
}